// round 14
// baseline (speedup 1.0000x reference)
#include <cuda_runtime.h>
#include <cuda_bf16.h>
#include <mma.h>
#include <cstdint>

using namespace nvcuda;

#define B_     128
#define L_     128
#define D_     512
#define C_     512
#define NODES_ 255
#define NLEAF  (B_ * L_)        // 16384
#define NINT   (B_ * (L_ - 1)) // 16256
#define W0_    0.01227184630308513f   // 2*pi/512

// Static device scratch (bf16 everywhere except output).
__device__ __nv_bfloat16 g_lbf[(size_t)NLEAF * D_];  // leaf vectors
__device__ __nv_bfloat16 g_wbf[(size_t)C_ * D_];     // lin_w bf16
__device__ __nv_bfloat16 g_Wf [(size_t)D_ * D_];     // fwd DFT  [col][d]
__device__ __nv_bfloat16 g_WiT[(size_t)D_ * D_];     // inv DFT transposed [kf][n]
__device__ __nv_bfloat16 g_Wc [(size_t)C_ * D_];     // lin_w @ WiT  [c][kf]
__device__ __nv_bfloat16 g_F  [(size_t)NLEAF * D_];  // leaf spectra [Re0..256|Im1..255]
__device__ __nv_bfloat16 g_P  [(size_t)NINT * D_];   // conj(Fa)*Fb packed

// ---------------------------------------------------------------------------
// Small prep kernels
// ---------------------------------------------------------------------------
__global__ void k_embed(const int* __restrict__ ids, const float* __restrict__ emb) {
    int bl = blockIdx.x;
    int t  = threadIdx.x;
    int id = ids[bl];
    float4 v = reinterpret_cast<const float4*>(emb + (size_t)id * D_)[t];
    __nv_bfloat162 p0 = __floats2bfloat162_rn(v.x, v.y);
    __nv_bfloat162 p1 = __floats2bfloat162_rn(v.z, v.w);
    uint2 pk;
    pk.x = *reinterpret_cast<unsigned*>(&p0);
    pk.y = *reinterpret_cast<unsigned*>(&p1);
    reinterpret_cast<uint2*>(g_lbf + (size_t)bl * D_)[t] = pk;
}

__global__ void k_cvt_w(const float* __restrict__ w) {
    int i = blockIdx.x * blockDim.x + threadIdx.x;
    float4 v = reinterpret_cast<const float4*>(w)[i];
    __nv_bfloat162 p0 = __floats2bfloat162_rn(v.x, v.y);
    __nv_bfloat162 p1 = __floats2bfloat162_rn(v.z, v.w);
    uint2 pk;
    pk.x = *reinterpret_cast<unsigned*>(&p0);
    pk.y = *reinterpret_cast<unsigned*>(&p1);
    reinterpret_cast<uint2*>(g_wbf)[i] = pk;
}

// Wf[col][d]: col<=256 -> cos(2pi*col*d/512); col>=257 -> -sin(2pi*(col-256)*d/512)
__global__ void k_gen_wf() {
    int i = blockIdx.x * 256 + threadIdx.x;
    int col = i >> 9, d = i & 511;
    float v;
    if (col < 257) { int t = (col * d) & 511; v = cosf(t * W0_); }
    else           { int t = ((col - 256) * d) & 511; v = -sinf(t * W0_); }
    g_Wf[i] = __float2bfloat16(v);
}

// WiT[kf][n]: kf<=256 (k=kf): sc*cos(2pi*k*n/512); kf>=257: -(2/512)*sin(2pi*(kf-256)*n/512)
__global__ void k_gen_wit() {
    int i = blockIdx.x * 256 + threadIdx.x;
    int kf = i >> 9, n = i & 511;
    float v;
    if (kf < 257) {
        float sc = (kf == 0 || kf == 256) ? (1.0f / 512.0f) : (2.0f / 512.0f);
        int t = (kf * n) & 511;
        v = sc * cosf(t * W0_);
    } else {
        int t = ((kf - 256) * n) & 511;
        v = -(2.0f / 512.0f) * sinf(t * W0_);
    }
    g_WiT[i] = __float2bfloat16(v);
}

// ---------------------------------------------------------------------------
// Pointwise P = conj(Fa)*Fb, packed layout [Re0..Re256 | Im1..Im255].
// ---------------------------------------------------------------------------
__device__ __forceinline__ void unpack8(uint4 u, float* f) {
    __nv_bfloat162* h = reinterpret_cast<__nv_bfloat162*>(&u);
#pragma unroll
    for (int q = 0; q < 4; q++) {
        float2 t = __bfloat1622float2(h[q]);
        f[2 * q] = t.x; f[2 * q + 1] = t.y;
    }
}
__device__ __forceinline__ uint4 pack8(const float* f) {
    uint4 u;
    __nv_bfloat162 h0 = __floats2bfloat162_rn(f[0], f[1]);
    __nv_bfloat162 h1 = __floats2bfloat162_rn(f[2], f[3]);
    __nv_bfloat162 h2 = __floats2bfloat162_rn(f[4], f[5]);
    __nv_bfloat162 h3 = __floats2bfloat162_rn(f[6], f[7]);
    u.x = *reinterpret_cast<unsigned*>(&h0);
    u.y = *reinterpret_cast<unsigned*>(&h1);
    u.z = *reinterpret_cast<unsigned*>(&h2);
    u.w = *reinterpret_cast<unsigned*>(&h3);
    return u;
}

__global__ __launch_bounds__(128) void k_pw(const int* __restrict__ comp) {
    int node = blockIdx.x * 4 + (threadIdx.x >> 5);
    int lane = threadIdx.x & 31;
    int b    = node / 127;
    int li   = comp[2 * node];
    int ri   = comp[2 * node + 1];

    const __nv_bfloat16* Fa = g_F + (size_t)(b * 128 + li) * D_;
    const __nv_bfloat16* Fb = g_F + (size_t)(b * 128 + ri) * D_;
    __nv_bfloat16*       P  = g_P + (size_t)node * D_;

    int c = 8 * lane;
    float ar[8], ai[8], br[8], bi[8];
    unpack8(*reinterpret_cast<const uint4*>(Fa + c),       ar);
    unpack8(*reinterpret_cast<const uint4*>(Fa + 256 + c), ai);
    unpack8(*reinterpret_cast<const uint4*>(Fb + c),       br);
    unpack8(*reinterpret_cast<const uint4*>(Fb + 256 + c), bi);

    float re256a = ai[0], re256b = bi[0];
    if (lane == 0) { ai[0] = 0.0f; bi[0] = 0.0f; }

    float pr[8], pi[8];
#pragma unroll
    for (int q = 0; q < 8; q++) {
        pr[q] = fmaf(ar[q], br[q],  ai[q] * bi[q]);
        pi[q] = fmaf(ar[q], bi[q], -ai[q] * br[q]);
    }
    if (lane == 0) pi[0] = re256a * re256b;

    *reinterpret_cast<uint4*>(P + c)       = pack8(pr);
    *reinterpret_cast<uint4*>(P + 256 + c) = pack8(pi);
}

// ===========================================================================
// cp.async 4-stage pipelined WMMA GEMM (R12 config + occupancy fixes).
// C[128x128] = A[128x512] * B[128x512]^T, bf16 x bf16 -> fp32.
// 256 threads = 8 warps (4M x 2N), warp tile 32x64 (2x4 frags).
// __launch_bounds__(256,2) caps regs at 128 -> 2 CTAs/SM (16 warps/SM).
// Inner loop streams A-frags one at a time (live operands ~40 regs).
// ONE __syncthreads per K-iteration (4-stage ring: stage s rewritten at
// iter s+1, strictly after the barrier that follows all reads of s).
// MODE 0: bf16 rows to outp (ld 512)
// MODE 2: bias+sigmoid, scatter internal-node rows
// MODE 3: bias+sigmoid, scatter leaf rows
// ===========================================================================
#define SK        40                 // smem row stride (bf16): 80B, 16B-multiple
#define STG       4
#define STAGE_EL  (128 * SK)         // elements per stage per matrix
#define STAGE_BY  (STAGE_EL * 2)     // bytes per stage per matrix
#define SMEMB     (STG * STAGE_BY * 2)   // 81920 bytes

__device__ __forceinline__ uint32_t smem_u32(const void* p) {
    return (uint32_t)__cvta_generic_to_shared(p);
}
__device__ __forceinline__ void cp16(uint32_t dst, const void* src) {
    asm volatile("cp.async.cg.shared.global [%0], [%1], 16;" :: "r"(dst), "l"(src));
}

template <int MODE>
__global__ __launch_bounds__(256, 2) void k_gemm(const __nv_bfloat16* __restrict__ A,
                                                 const __nv_bfloat16* __restrict__ Bm,
                                                 const float* __restrict__ lb,
                                                 void* __restrict__ outp) {
    extern __shared__ __nv_bfloat16 dsm[];
    __nv_bfloat16* sA = dsm;                      // [STG][128*SK]
    __nv_bfloat16* sB = dsm + STG * STAGE_EL;

    int tid  = threadIdx.x;
    int warp = tid >> 5;
    int lane = tid & 31;
    int wm   = warp & 3;           // 0..3 (M, 32 rows)
    int wn   = warp >> 2;          // 0..1 (N, 64 cols)
    int m0   = blockIdx.y * 128;
    int n0   = blockIdx.x * 128;

    // staging map: thread -> row (0..127), two 16B chunks at c16base, c16base+1
    int row     = tid >> 1;
    int c16base = (tid & 1) * 2;

    const __nv_bfloat16* gA = A  + (size_t)(m0 + row) * D_ + c16base * 8;
    const __nv_bfloat16* gB = Bm + (size_t)(n0 + row) * D_ + c16base * 8;
    uint32_t dA = smem_u32(sA + row * SK + c16base * 8);
    uint32_t dB = smem_u32(sB + row * SK + c16base * 8);

#define PF(s, kt)                                                             \
    do {                                                                      \
        cp16(dA + (s) * STAGE_BY, gA + (kt) * 32);                            \
        cp16(dA + (s) * STAGE_BY + 16, gA + (kt) * 32 + 8);                   \
        cp16(dB + (s) * STAGE_BY, gB + (kt) * 32);                            \
        cp16(dB + (s) * STAGE_BY + 16, gB + (kt) * 32 + 8);                   \
    } while (0)

    wmma::fragment<wmma::accumulator, 16, 16, 16, float> acc[2][4];
#pragma unroll
    for (int mi = 0; mi < 2; mi++)
#pragma unroll
        for (int ni = 0; ni < 4; ni++)
            wmma::fill_fragment(acc[mi][ni], 0.0f);

    PF(0, 0); asm volatile("cp.async.commit_group;");
    PF(1, 1); asm volatile("cp.async.commit_group;");
    PF(2, 2); asm volatile("cp.async.commit_group;");

    for (int kt = 0; kt < 16; kt++) {
        asm volatile("cp.async.wait_group 2;");
        __syncthreads();

        int cur = kt & 3;
        const __nv_bfloat16* cA = sA + cur * STAGE_EL;
        const __nv_bfloat16* cB = sB + cur * STAGE_EL;
#pragma unroll
        for (int ks = 0; ks < 2; ks++) {
            wmma::fragment<wmma::matrix_b, 16, 16, 16, __nv_bfloat16, wmma::col_major> bf[4];
#pragma unroll
            for (int ni = 0; ni < 4; ni++)
                wmma::load_matrix_sync(bf[ni], &cB[(wn * 64 + ni * 16) * SK + ks * 16], SK);
#pragma unroll
            for (int mi = 0; mi < 2; mi++) {
                wmma::fragment<wmma::matrix_a, 16, 16, 16, __nv_bfloat16, wmma::row_major> af;
                wmma::load_matrix_sync(af, &cA[(wm * 32 + mi * 16) * SK + ks * 16], SK);
#pragma unroll
                for (int ni = 0; ni < 4; ni++)
                    wmma::mma_sync(acc[mi][ni], af, bf[ni], acc[mi][ni]);
            }
        }

        // prefetch AFTER compute: stage (kt+3)&3 is rewritten only after the
        // barrier following all reads of it (single-barrier-safe with 4 stages)
        if (kt + 3 < 16) PF((kt + 3) & 3, kt + 3);
        asm volatile("cp.async.commit_group;");
    }
#undef PF

    // Epilogue: per-warp 16x20 fp32 bounce in (now free) stage smem.
    __syncthreads();
    float* Csw = reinterpret_cast<float*>(dsm) + warp * 320;
    int er = lane >> 1;
    int ec = (lane & 1) * 8;
#pragma unroll
    for (int mi = 0; mi < 2; mi++) {
#pragma unroll
        for (int ni = 0; ni < 4; ni++) {
            __syncwarp();
            wmma::store_matrix_sync(Csw, acc[mi][ni], 20, wmma::mem_row_major);
            __syncwarp();
            int gn = n0 + wn * 64 + ni * 16 + ec;
            int gm = m0 + wm * 32 + mi * 16 + er;
            if (MODE == 0) {
                __nv_bfloat162 p0 = __floats2bfloat162_rn(Csw[er * 20 + ec + 0], Csw[er * 20 + ec + 1]);
                __nv_bfloat162 p1 = __floats2bfloat162_rn(Csw[er * 20 + ec + 2], Csw[er * 20 + ec + 3]);
                __nv_bfloat162 p2 = __floats2bfloat162_rn(Csw[er * 20 + ec + 4], Csw[er * 20 + ec + 5]);
                __nv_bfloat162 p3 = __floats2bfloat162_rn(Csw[er * 20 + ec + 6], Csw[er * 20 + ec + 7]);
                uint4 pk;
                pk.x = *reinterpret_cast<unsigned*>(&p0);
                pk.y = *reinterpret_cast<unsigned*>(&p1);
                pk.z = *reinterpret_cast<unsigned*>(&p2);
                pk.w = *reinterpret_cast<unsigned*>(&p3);
                *reinterpret_cast<uint4*>(
                    reinterpret_cast<__nv_bfloat16*>(outp) + (size_t)gm * D_ + gn) = pk;
            } else {
                int orow;
                if (MODE == 2) {
                    int bb = gm / 127;
                    int ss = gm - bb * 127;
                    orow = bb * NODES_ + L_ + ss;
                } else {
                    orow = (gm >> 7) * NODES_ + (gm & 127);
                }
                float4 b0 = *reinterpret_cast<const float4*>(&lb[gn]);
                float4 b1 = *reinterpret_cast<const float4*>(&lb[gn + 4]);
                float o[8];
#pragma unroll
                for (int j = 0; j < 8; j++) o[j] = Csw[er * 20 + ec + j];
                o[0] += b0.x; o[1] += b0.y; o[2] += b0.z; o[3] += b0.w;
                o[4] += b1.x; o[5] += b1.y; o[6] += b1.z; o[7] += b1.w;
#pragma unroll
                for (int j = 0; j < 8; j++) o[j] = 1.0f / (1.0f + __expf(-o[j]));
                float* op = reinterpret_cast<float*>(outp) + (size_t)orow * C_ + gn;
                *reinterpret_cast<float4*>(op)     = make_float4(o[0], o[1], o[2], o[3]);
                *reinterpret_cast<float4*>(op + 4) = make_float4(o[4], o[5], o[6], o[7]);
            }
        }
    }
}

// ---------------------------------------------------------------------------
// Launch
// ---------------------------------------------------------------------------
extern "C" void kernel_launch(void* const* d_in, const int* in_sizes, int n_in,
                              void* d_out, int out_size) {
    const int*   ids  = nullptr;
    const int*   comp = nullptr;
    const float* emb  = nullptr;
    const float* lw   = nullptr;
    const float* lb   = nullptr;

    for (int i = 0; i < n_in; i++) {
        switch (in_sizes[i]) {
            case 16384:    ids  = (const int*)d_in[i];   break;  // leaf_content_id [B,L]
            case 32512:    comp = (const int*)d_in[i];   break;  // composition_info [B,127,2]
            case 25600000: emb  = (const float*)d_in[i]; break;  // emb_weight [V,D]
            case 262144:   lw   = (const float*)d_in[i]; break;  // lin_w [C,D]
            case 512:      lb   = (const float*)d_in[i]; break;  // lin_b [C]
            default: break;                                       // content_mask (unused)
        }
    }

    float* out = (float*)d_out;

    // device-symbol addresses (host side; not stream ops -> capture-safe)
    __nv_bfloat16 *p_lbf, *p_wbf, *p_Wf, *p_WiT, *p_Wc, *p_F, *p_P;
    cudaGetSymbolAddress((void**)&p_lbf, g_lbf);
    cudaGetSymbolAddress((void**)&p_wbf, g_wbf);
    cudaGetSymbolAddress((void**)&p_Wf,  g_Wf);
    cudaGetSymbolAddress((void**)&p_WiT, g_WiT);
    cudaGetSymbolAddress((void**)&p_Wc,  g_Wc);
    cudaGetSymbolAddress((void**)&p_F,   g_F);
    cudaGetSymbolAddress((void**)&p_P,   g_P);

    // opt-in to 80KB dynamic smem (attribute set: not a stream op, capture-safe)
    static bool attr_done = false;
    if (!attr_done) {
        cudaFuncSetAttribute(k_gemm<0>, cudaFuncAttributeMaxDynamicSharedMemorySize, SMEMB);
        cudaFuncSetAttribute(k_gemm<2>, cudaFuncAttributeMaxDynamicSharedMemorySize, SMEMB);
        cudaFuncSetAttribute(k_gemm<3>, cudaFuncAttributeMaxDynamicSharedMemorySize, SMEMB);
        attr_done = true;
    }

    k_embed  <<<NLEAF, 128>>>(ids, emb);
    k_cvt_w  <<<256, 256>>>(lw);
    k_gen_wf <<<(D_ * D_) / 256, 256>>>();
    k_gen_wit<<<(D_ * D_) / 256, 256>>>();

    k_gemm<0><<<dim3(4, 4),           256, SMEMB>>>(p_wbf, p_WiT, lb, (void*)p_Wc);  // Wc
    k_gemm<0><<<dim3(4, NLEAF / 128), 256, SMEMB>>>(p_lbf, p_Wf,  lb, (void*)p_F);   // fwd FFT
    k_pw     <<<NINT / 4, 128>>>(comp);
    k_gemm<2><<<dim3(4, NINT / 128),  256, SMEMB>>>(p_P,   p_Wc,  lb, (void*)out);   // inv+logits
    k_gemm<3><<<dim3(4, NLEAF / 128), 256, SMEMB>>>(p_lbf, p_wbf, lb, (void*)out);   // leaf logits
}

// round 15
// speedup vs baseline: 1.4252x; 1.4252x over previous
#include <cuda_runtime.h>
#include <cuda_bf16.h>
#include <cuda_fp16.h>
#include <cuda_fp8.h>
#include <mma.h>
#include <cstdint>

using namespace nvcuda;

#define B_     128
#define L_     128
#define D_     512
#define C_     512
#define NODES_ 255
#define NLEAF  (B_ * L_)        // 16384
#define NINT   (B_ * (L_ - 1)) // 16256
#define W0_    0.01227184630308513f   // 2*pi/512

// Scratch. fp8 operands for big GEMMs; bf16 kept only for the tiny Wc GEMM.
__device__ __align__(16) uint8_t g_lbf8[(size_t)NLEAF * D_]; // leaf fp8 (x64)
__device__ __align__(16) uint8_t g_w8  [(size_t)C_ * D_];    // lin_w fp8 (x64)
__device__ __align__(16) uint8_t g_Wf8 [(size_t)D_ * D_];    // fwd DFT fp8 (x1)
__device__ __align__(16) uint8_t g_Wc8 [(size_t)C_ * D_];    // Wc fp8 (x256)
__device__ __align__(16) uint8_t g_F8  [(size_t)NLEAF * D_]; // leaf spectra fp8
__device__ __align__(16) uint8_t g_P8  [(size_t)NINT * D_];  // conj(Fa)*Fb fp8
__device__ __nv_bfloat16 g_wbf[(size_t)C_ * D_];             // lin_w bf16 (Wc GEMM)
__device__ __nv_bfloat16 g_WiT[(size_t)D_ * D_];             // inv DFT^T bf16
__device__ __nv_bfloat16 g_Wc [(size_t)C_ * D_];             // Wc bf16

// ---------------------------------------------------------------------------
// fp8 pack/unpack helpers (e4m3). pack: a->upper byte, b->lower byte.
// ---------------------------------------------------------------------------
__device__ __forceinline__ uint16_t pack_e4m3x2(float hi, float lo) {
    uint16_t r;
    asm("cvt.rn.satfinite.e4m3x2.f32 %0, %1, %2;" : "=h"(r) : "f"(hi), "f"(lo));
    return r;
}
__device__ __forceinline__ float2 unpack_e4m3x2(uint16_t v) {
    uint32_t h2;
    asm("cvt.rn.f16x2.e4m3x2 %0, %1;" : "=r"(h2) : "h"(v));
    __half2 h = *reinterpret_cast<__half2*>(&h2);
    return __half22float2(h);
}

// ---------------------------------------------------------------------------
// Prep kernels
// ---------------------------------------------------------------------------
__global__ void k_embed8(const int* __restrict__ ids, const float* __restrict__ emb) {
    int bl = blockIdx.x;
    int t  = threadIdx.x;                 // 0..127, 4 elems each
    int id = ids[bl];
    float4 v = reinterpret_cast<const float4*>(emb + (size_t)id * D_)[t];
    uint16_t lo = pack_e4m3x2(v.y * 64.0f, v.x * 64.0f);
    uint16_t hi = pack_e4m3x2(v.w * 64.0f, v.z * 64.0f);
    reinterpret_cast<uint32_t*>(g_lbf8 + (size_t)bl * D_)[t] =
        ((uint32_t)hi << 16) | lo;
}

__global__ void k_cvt_w(const float* __restrict__ w) {
    int i = blockIdx.x * blockDim.x + threadIdx.x;   // 65536 float4s
    float4 v = reinterpret_cast<const float4*>(w)[i];
    // bf16 copy (for Wc GEMM)
    __nv_bfloat162 p0 = __floats2bfloat162_rn(v.x, v.y);
    __nv_bfloat162 p1 = __floats2bfloat162_rn(v.z, v.w);
    uint2 pk;
    pk.x = *reinterpret_cast<unsigned*>(&p0);
    pk.y = *reinterpret_cast<unsigned*>(&p1);
    reinterpret_cast<uint2*>(g_wbf)[i] = pk;
    // fp8 copy (x64) for leaf-logits GEMM
    uint16_t lo = pack_e4m3x2(v.y * 64.0f, v.x * 64.0f);
    uint16_t hi = pack_e4m3x2(v.w * 64.0f, v.z * 64.0f);
    reinterpret_cast<uint32_t*>(g_w8)[i] = ((uint32_t)hi << 16) | lo;
}

// Wf[col][d] fp8: col<=256 -> cos; col>=257 -> -sin((col-256)d)
__global__ void k_gen_wf8() {
    int i = blockIdx.x * 256 + threadIdx.x;     // 0..131071, 2 d's each
    int col = i >> 8;
    int d0  = (i & 255) * 2;
    float v0, v1;
    if (col < 257) {
        v0 = cosf(((col * d0) & 511) * W0_);
        v1 = cosf(((col * (d0 + 1)) & 511) * W0_);
    } else {
        int k = col - 256;
        v0 = -sinf(((k * d0) & 511) * W0_);
        v1 = -sinf(((k * (d0 + 1)) & 511) * W0_);
    }
    reinterpret_cast<uint16_t*>(g_Wf8)[i] = pack_e4m3x2(v1, v0);
}

// WiT bf16 (feeds the bf16 Wc GEMM)
__global__ void k_gen_wit() {
    int i = blockIdx.x * 256 + threadIdx.x;
    int kf = i >> 9, n = i & 511;
    float v;
    if (kf < 257) {
        float sc = (kf == 0 || kf == 256) ? (1.0f / 512.0f) : (2.0f / 512.0f);
        v = sc * cosf(((kf * n) & 511) * W0_);
    } else {
        v = -(2.0f / 512.0f) * sinf((((kf - 256) * n) & 511) * W0_);
    }
    g_WiT[i] = __float2bfloat16(v);
}

// g_Wc (bf16) -> g_Wc8 (fp8, x256)
__global__ void k_wc_cvt() {
    int i = blockIdx.x * 256 + threadIdx.x;     // 32768 threads, 8 elems each
    uint4 u = reinterpret_cast<const uint4*>(g_Wc)[i];
    __nv_bfloat162* h = reinterpret_cast<__nv_bfloat162*>(&u);
    uint16_t o[4];
#pragma unroll
    for (int q = 0; q < 4; q++) {
        float2 f = __bfloat1622float2(h[q]);
        o[q] = pack_e4m3x2(f.y * 256.0f, f.x * 256.0f);
    }
    uint2 pk;
    pk.x = ((uint32_t)o[1] << 16) | o[0];
    pk.y = ((uint32_t)o[3] << 16) | o[2];
    reinterpret_cast<uint2*>(g_Wc8)[i] = pk;
}

// ---------------------------------------------------------------------------
// Pointwise P = conj(Fa)*Fb on fp8 spectra; packed [Re0..Re256 | Im1..Im255].
// ---------------------------------------------------------------------------
__device__ __forceinline__ void unpack8f(uint2 u, float* f) {
    uint16_t* h = reinterpret_cast<uint16_t*>(&u);
#pragma unroll
    for (int q = 0; q < 4; q++) {
        float2 t = unpack_e4m3x2(h[q]);
        f[2 * q] = t.x; f[2 * q + 1] = t.y;
    }
}
__device__ __forceinline__ uint2 pack8f(const float* f) {
    uint16_t o[4];
#pragma unroll
    for (int q = 0; q < 4; q++) o[q] = pack_e4m3x2(f[2 * q + 1], f[2 * q]);
    uint2 u;
    u.x = ((uint32_t)o[1] << 16) | o[0];
    u.y = ((uint32_t)o[3] << 16) | o[2];
    return u;
}

__global__ __launch_bounds__(128) void k_pw8(const int* __restrict__ comp) {
    int node = blockIdx.x * 4 + (threadIdx.x >> 5);
    int lane = threadIdx.x & 31;
    int b    = node / 127;
    int li   = comp[2 * node];
    int ri   = comp[2 * node + 1];

    const uint8_t* Fa = g_F8 + (size_t)(b * 128 + li) * D_;
    const uint8_t* Fb = g_F8 + (size_t)(b * 128 + ri) * D_;
    uint8_t*       P  = g_P8 + (size_t)node * D_;

    int c = 8 * lane;
    float ar[8], ai[8], br[8], bi[8];
    unpack8f(*reinterpret_cast<const uint2*>(Fa + c),       ar);
    unpack8f(*reinterpret_cast<const uint2*>(Fa + 256 + c), ai);
    unpack8f(*reinterpret_cast<const uint2*>(Fb + c),       br);
    unpack8f(*reinterpret_cast<const uint2*>(Fb + 256 + c), bi);

    float re256a = ai[0], re256b = bi[0];
    if (lane == 0) { ai[0] = 0.0f; bi[0] = 0.0f; }

    float pr[8], pi[8];
#pragma unroll
    for (int q = 0; q < 8; q++) {
        pr[q] = fmaf(ar[q], br[q],  ai[q] * bi[q]);
        pi[q] = fmaf(ar[q], bi[q], -ai[q] * br[q]);
    }
    if (lane == 0) pi[0] = re256a * re256b;

    *reinterpret_cast<uint2*>(P + c)       = pack8f(pr);
    *reinterpret_cast<uint2*>(P + 256 + c) = pack8f(pi);
}

// ===========================================================================
// bf16 WMMA GEMM (R12 engine) — used ONLY for the tiny Wc GEMM (16 blocks).
// ===========================================================================
#define SK        40
#define STG       4
#define STAGE_EL  (128 * SK)
#define STAGE_BY  (STAGE_EL * 2)
#define SMEMB     (STG * STAGE_BY * 2)   // 81920 bytes

__device__ __forceinline__ uint32_t smem_u32(const void* p) {
    return (uint32_t)__cvta_generic_to_shared(p);
}
__device__ __forceinline__ void cp16(uint32_t dst, const void* src) {
    asm volatile("cp.async.cg.shared.global [%0], [%1], 16;" :: "r"(dst), "l"(src));
}

__global__ __launch_bounds__(256) void k_gemm_bf(const __nv_bfloat16* __restrict__ A,
                                                 const __nv_bfloat16* __restrict__ Bm,
                                                 __nv_bfloat16* __restrict__ outp) {
    extern __shared__ __nv_bfloat16 dsm[];
    __nv_bfloat16* sA = dsm;
    __nv_bfloat16* sB = dsm + STG * STAGE_EL;

    int tid  = threadIdx.x;
    int warp = tid >> 5;
    int lane = tid & 31;
    int wm   = warp & 3;
    int wn   = warp >> 2;
    int m0   = blockIdx.y * 128;
    int n0   = blockIdx.x * 128;

    int row     = tid >> 1;
    int c16base = (tid & 1) * 2;
    const __nv_bfloat16* gA = A  + (size_t)(m0 + row) * D_ + c16base * 8;
    const __nv_bfloat16* gB = Bm + (size_t)(n0 + row) * D_ + c16base * 8;
    uint32_t dA = smem_u32(sA + row * SK + c16base * 8);
    uint32_t dB = smem_u32(sB + row * SK + c16base * 8);

#define PFB(s, kt)                                                            \
    do {                                                                      \
        cp16(dA + (s) * STAGE_BY, gA + (kt) * 32);                            \
        cp16(dA + (s) * STAGE_BY + 16, gA + (kt) * 32 + 8);                   \
        cp16(dB + (s) * STAGE_BY, gB + (kt) * 32);                            \
        cp16(dB + (s) * STAGE_BY + 16, gB + (kt) * 32 + 8);                   \
    } while (0)

    wmma::fragment<wmma::accumulator, 16, 16, 16, float> acc[2][4];
#pragma unroll
    for (int mi = 0; mi < 2; mi++)
#pragma unroll
        for (int ni = 0; ni < 4; ni++)
            wmma::fill_fragment(acc[mi][ni], 0.0f);

    PFB(0, 0); asm volatile("cp.async.commit_group;");
    PFB(1, 1); asm volatile("cp.async.commit_group;");
    PFB(2, 2); asm volatile("cp.async.commit_group;");

    for (int kt = 0; kt < 16; kt++) {
        asm volatile("cp.async.wait_group 2;");
        __syncthreads();
        if (kt + 3 < 16) PFB((kt + 3) & 3, kt + 3);
        asm volatile("cp.async.commit_group;");

        int cur = kt & 3;
        const __nv_bfloat16* cA = sA + cur * STAGE_EL;
        const __nv_bfloat16* cB = sB + cur * STAGE_EL;
#pragma unroll
        for (int ks = 0; ks < 2; ks++) {
            wmma::fragment<wmma::matrix_a, 16, 16, 16, __nv_bfloat16, wmma::row_major> af[2];
            wmma::fragment<wmma::matrix_b, 16, 16, 16, __nv_bfloat16, wmma::col_major> bf[4];
#pragma unroll
            for (int mi = 0; mi < 2; mi++)
                wmma::load_matrix_sync(af[mi], &cA[(wm * 32 + mi * 16) * SK + ks * 16], SK);
#pragma unroll
            for (int ni = 0; ni < 4; ni++)
                wmma::load_matrix_sync(bf[ni], &cB[(wn * 64 + ni * 16) * SK + ks * 16], SK);
#pragma unroll
            for (int mi = 0; mi < 2; mi++)
#pragma unroll
                for (int ni = 0; ni < 4; ni++)
                    wmma::mma_sync(acc[mi][ni], af[mi], bf[ni], acc[mi][ni]);
        }
        __syncthreads();
    }
#undef PFB

    float* Csw = reinterpret_cast<float*>(dsm) + warp * 320;
    int er = lane >> 1;
    int ec = (lane & 1) * 8;
#pragma unroll
    for (int mi = 0; mi < 2; mi++)
#pragma unroll
        for (int ni = 0; ni < 4; ni++) {
            __syncwarp();
            wmma::store_matrix_sync(Csw, acc[mi][ni], 20, wmma::mem_row_major);
            __syncwarp();
            int gn = n0 + wn * 64 + ni * 16 + ec;
            int gm = m0 + wm * 32 + mi * 16 + er;
            __nv_bfloat162 p0 = __floats2bfloat162_rn(Csw[er * 20 + ec + 0], Csw[er * 20 + ec + 1]);
            __nv_bfloat162 p1 = __floats2bfloat162_rn(Csw[er * 20 + ec + 2], Csw[er * 20 + ec + 3]);
            __nv_bfloat162 p2 = __floats2bfloat162_rn(Csw[er * 20 + ec + 4], Csw[er * 20 + ec + 5]);
            __nv_bfloat162 p3 = __floats2bfloat162_rn(Csw[er * 20 + ec + 6], Csw[er * 20 + ec + 7]);
            uint4 pk;
            pk.x = *reinterpret_cast<unsigned*>(&p0);
            pk.y = *reinterpret_cast<unsigned*>(&p1);
            pk.z = *reinterpret_cast<unsigned*>(&p2);
            pk.w = *reinterpret_cast<unsigned*>(&p3);
            *reinterpret_cast<uint4*>(outp + (size_t)gm * D_ + gn) = pk;
        }
}

// ===========================================================================
// FP8 e4m3 GEMM: C[128x128] = A[128x512] * B[128x512]^T, fp32 accum.
// mma.m16n8k32; 8 warps (4M x 2N); warp tile 32x64 = 2 m-frags x 8 n-frags.
// cp.async 4-stage ring, BK=64 bytes, 8 K-iterations. Row stride 80B
// (conflict-free: banks 20g+tig all distinct).
// MODE 0: store fp8 spectra (scale 1/64)
// MODE 2: internal logits: sigmoid(acc/256 + b), scatter
// MODE 3: leaf logits:     sigmoid(acc/4096 + b), scatter
// ===========================================================================
#define SK8       80                  // bytes per row in smem
#define STAGE8    (128 * SK8)         // 10240 bytes per stage per matrix
#define SMEMB8    (STG * STAGE8 * 2)  // 81920 bytes

__device__ __forceinline__ void mma8(float* c, uint32_t a0, uint32_t a1,
                                     uint32_t a2, uint32_t a3,
                                     uint32_t b0, uint32_t b1) {
    asm volatile(
        "mma.sync.aligned.m16n8k32.row.col.f32.e4m3.e4m3.f32 "
        "{%0,%1,%2,%3}, {%4,%5,%6,%7}, {%8,%9}, {%0,%1,%2,%3};"
        : "+f"(c[0]), "+f"(c[1]), "+f"(c[2]), "+f"(c[3])
        : "r"(a0), "r"(a1), "r"(a2), "r"(a3), "r"(b0), "r"(b1));
}

template <int MODE>
__global__ __launch_bounds__(256) void k_gemm8(const uint8_t* __restrict__ A,
                                               const uint8_t* __restrict__ Bm,
                                               const float* __restrict__ lb,
                                               void* __restrict__ outp) {
    extern __shared__ char dsm8[];
    char* sA = dsm8;                      // [STG][128*SK8]
    char* sB = dsm8 + STG * STAGE8;

    int tid  = threadIdx.x;
    int warp = tid >> 5;
    int lane = tid & 31;
    int g    = lane >> 2;                 // 0..7
    int tig  = lane & 3;                  // 0..3
    int wm   = warp & 3;                  // M: 32 rows each
    int wn   = warp >> 2;                 // N: 64 cols each
    int m0   = blockIdx.y * 128;
    int n0   = blockIdx.x * 128;

    // staging: thread handles chunks tid and tid+256 (rows r, r+64)
    int srow = tid >> 2;
    int sc16 = tid & 3;
    const uint8_t* gA = A  + (size_t)(m0 + srow) * D_ + sc16 * 16;
    const uint8_t* gB = Bm + (size_t)(n0 + srow) * D_ + sc16 * 16;
    uint32_t dA = smem_u32(sA + srow * SK8 + sc16 * 16);
    uint32_t dB = smem_u32(sB + srow * SK8 + sc16 * 16);

#define PF8(s, kt)                                                            \
    do {                                                                      \
        cp16(dA + (s) * STAGE8, gA + (kt) * 64);                              \
        cp16(dA + (s) * STAGE8 + 64 * SK8, gA + (kt) * 64 + (size_t)64 * D_); \
        cp16(dB + (s) * STAGE8, gB + (kt) * 64);                              \
        cp16(dB + (s) * STAGE8 + 64 * SK8, gB + (kt) * 64 + (size_t)64 * D_); \
    } while (0)

    float acc[2][8][4];
#pragma unroll
    for (int mi = 0; mi < 2; mi++)
#pragma unroll
        for (int nj = 0; nj < 8; nj++)
#pragma unroll
            for (int q = 0; q < 4; q++) acc[mi][nj][q] = 0.0f;

    PF8(0, 0); asm volatile("cp.async.commit_group;");
    PF8(1, 1); asm volatile("cp.async.commit_group;");
    PF8(2, 2); asm volatile("cp.async.commit_group;");

    for (int kt = 0; kt < 8; kt++) {
        asm volatile("cp.async.wait_group 2;");
        __syncthreads();
        if (kt + 3 < 8) PF8((kt + 3) & 3, kt + 3);
        asm volatile("cp.async.commit_group;");

        int cur = kt & 3;
        const char* cA = sA + cur * STAGE8;
        const char* cB = sB + cur * STAGE8;
#pragma unroll
        for (int kc = 0; kc < 2; kc++) {
            uint32_t bfr[8][2];
#pragma unroll
            for (int nj = 0; nj < 8; nj++) {
                const char* pb = cB + (wn * 64 + 8 * nj + g) * SK8 + kc * 32 + 4 * tig;
                bfr[nj][0] = *reinterpret_cast<const uint32_t*>(pb);
                bfr[nj][1] = *reinterpret_cast<const uint32_t*>(pb + 16);
            }
#pragma unroll
            for (int mi = 0; mi < 2; mi++) {
                const char* pa = cA + (wm * 32 + mi * 16 + g) * SK8 + kc * 32 + 4 * tig;
                uint32_t a0 = *reinterpret_cast<const uint32_t*>(pa);
                uint32_t a1 = *reinterpret_cast<const uint32_t*>(pa + 8 * SK8);
                uint32_t a2 = *reinterpret_cast<const uint32_t*>(pa + 16);
                uint32_t a3 = *reinterpret_cast<const uint32_t*>(pa + 8 * SK8 + 16);
#pragma unroll
                for (int nj = 0; nj < 8; nj++)
                    mma8(acc[mi][nj], a0, a1, a2, a3, bfr[nj][0], bfr[nj][1]);
            }
        }
        __syncthreads();
    }
#undef PF8

    // Epilogue (fragment-direct: rows g, g+8; cols 2*tig, 2*tig+1)
    const float s = (MODE == 0) ? (1.0f / 64.0f)
                  : (MODE == 2) ? (1.0f / 256.0f) : (1.0f / 4096.0f);
#pragma unroll
    for (int mi = 0; mi < 2; mi++) {
#pragma unroll
        for (int nj = 0; nj < 8; nj++) {
            int col = n0 + wn * 64 + 8 * nj + 2 * tig;
            int r0  = m0 + wm * 32 + mi * 16 + g;
            float c0 = acc[mi][nj][0] * s, c1 = acc[mi][nj][1] * s;
            float c2 = acc[mi][nj][2] * s, c3 = acc[mi][nj][3] * s;
            if (MODE == 0) {
                uint8_t* ob = reinterpret_cast<uint8_t*>(outp);
                *reinterpret_cast<uint16_t*>(ob + (size_t)r0 * D_ + col) =
                    pack_e4m3x2(c1, c0);
                *reinterpret_cast<uint16_t*>(ob + (size_t)(r0 + 8) * D_ + col) =
                    pack_e4m3x2(c3, c2);
            } else {
                float2 bb = *reinterpret_cast<const float2*>(&lb[col]);
#pragma unroll
                for (int h = 0; h < 2; h++) {
                    int gm = r0 + 8 * h;
                    int orow;
                    if (MODE == 2) {
                        int bbx = gm / 127;
                        orow = bbx * NODES_ + L_ + (gm - bbx * 127);
                    } else {
                        orow = (gm >> 7) * NODES_ + (gm & 127);
                    }
                    float x0 = (h ? c2 : c0) + bb.x;
                    float x1 = (h ? c3 : c1) + bb.y;
                    float2 o;
                    o.x = 1.0f / (1.0f + __expf(-x0));
                    o.y = 1.0f / (1.0f + __expf(-x1));
                    *reinterpret_cast<float2*>(
                        reinterpret_cast<float*>(outp) + (size_t)orow * C_ + col) = o;
                }
            }
        }
    }
}

// ---------------------------------------------------------------------------
// Launch
// ---------------------------------------------------------------------------
extern "C" void kernel_launch(void* const* d_in, const int* in_sizes, int n_in,
                              void* d_out, int out_size) {
    const int*   ids  = nullptr;
    const int*   comp = nullptr;
    const float* emb  = nullptr;
    const float* lw   = nullptr;
    const float* lb   = nullptr;

    for (int i = 0; i < n_in; i++) {
        switch (in_sizes[i]) {
            case 16384:    ids  = (const int*)d_in[i];   break;  // leaf_content_id
            case 32512:    comp = (const int*)d_in[i];   break;  // composition_info
            case 25600000: emb  = (const float*)d_in[i]; break;  // emb_weight
            case 262144:   lw   = (const float*)d_in[i]; break;  // lin_w
            case 512:      lb   = (const float*)d_in[i]; break;  // lin_b
            default: break;                                       // content_mask
        }
    }

    float* out = (float*)d_out;

    __nv_bfloat16 *p_wbf, *p_WiT, *p_Wc;
    uint8_t *p_lbf8, *p_w8, *p_Wf8, *p_Wc8, *p_F8, *p_P8;
    cudaGetSymbolAddress((void**)&p_wbf,  g_wbf);
    cudaGetSymbolAddress((void**)&p_WiT,  g_WiT);
    cudaGetSymbolAddress((void**)&p_Wc,   g_Wc);
    cudaGetSymbolAddress((void**)&p_lbf8, g_lbf8);
    cudaGetSymbolAddress((void**)&p_w8,   g_w8);
    cudaGetSymbolAddress((void**)&p_Wf8,  g_Wf8);
    cudaGetSymbolAddress((void**)&p_Wc8,  g_Wc8);
    cudaGetSymbolAddress((void**)&p_F8,   g_F8);
    cudaGetSymbolAddress((void**)&p_P8,   g_P8);

    static bool attr_done = false;
    if (!attr_done) {
        cudaFuncSetAttribute(k_gemm_bf,  cudaFuncAttributeMaxDynamicSharedMemorySize, SMEMB);
        cudaFuncSetAttribute(k_gemm8<0>, cudaFuncAttributeMaxDynamicSharedMemorySize, SMEMB8);
        cudaFuncSetAttribute(k_gemm8<2>, cudaFuncAttributeMaxDynamicSharedMemorySize, SMEMB8);
        cudaFuncSetAttribute(k_gemm8<3>, cudaFuncAttributeMaxDynamicSharedMemorySize, SMEMB8);
        attr_done = true;
    }

    k_embed8 <<<NLEAF, 128>>>(ids, emb);
    k_cvt_w  <<<256, 256>>>(lw);
    k_gen_wf8<<<512, 256>>>();
    k_gen_wit<<<1024, 256>>>();

    k_gemm_bf<<<dim3(4, 4), 256, SMEMB>>>(p_wbf, p_WiT, p_Wc);                // Wc bf16
    k_wc_cvt <<<128, 256>>>();                                                 // Wc -> fp8
    k_gemm8<0><<<dim3(4, NLEAF / 128), 256, SMEMB8>>>(p_lbf8, p_Wf8, lb, (void*)p_F8);
    k_pw8    <<<NINT / 4, 128>>>(comp);
    k_gemm8<2><<<dim3(4, NINT / 128),  256, SMEMB8>>>(p_P8,   p_Wc8, lb, (void*)out);
    k_gemm8<3><<<dim3(4, NLEAF / 128), 256, SMEMB8>>>(p_lbf8, p_w8,  lb, (void*)out);
}

// round 16
// speedup vs baseline: 1.4859x; 1.0426x over previous
#include <cuda_runtime.h>
#include <cuda_bf16.h>
#include <cuda_fp16.h>
#include <cuda_fp8.h>
#include <mma.h>
#include <cstdint>

using namespace nvcuda;

#define B_     128
#define L_     128
#define D_     512
#define C_     512
#define NODES_ 255
#define NLEAF  (B_ * L_)        // 16384
#define NINT   (B_ * (L_ - 1)) // 16256
#define NALL   (NLEAF + NINT)   // 32640
#define W0_    0.01227184630308513f   // 2*pi/512

// Scratch.
__device__ __align__(16) uint8_t g_lbf8[(size_t)NLEAF * D_]; // leaf fp8 (x64)
__device__ __align__(16) uint8_t g_Wf8 [(size_t)D_ * D_];    // fwd DFT fp8 (x1)
__device__ __align__(16) uint8_t g_Wc8 [(size_t)C_ * D_];    // Wc fp8 (x256)
__device__ __align__(16) uint8_t g_S8  [(size_t)NALL * D_];  // [leaf spectra; P spectra]
__device__ __nv_bfloat16 g_wbf[(size_t)C_ * D_];             // lin_w bf16 (Wc GEMM)
__device__ __nv_bfloat16 g_WiT[(size_t)D_ * D_];             // inv DFT^T bf16
__device__ __nv_bfloat16 g_Wc [(size_t)C_ * D_];             // Wc bf16

// ---------------------------------------------------------------------------
// fp8 helpers (e4m3)
// ---------------------------------------------------------------------------
__device__ __forceinline__ uint16_t pack_e4m3x2(float hi, float lo) {
    uint16_t r;
    asm("cvt.rn.satfinite.e4m3x2.f32 %0, %1, %2;" : "=h"(r) : "f"(hi), "f"(lo));
    return r;
}
__device__ __forceinline__ float2 unpack_e4m3x2(uint16_t v) {
    uint32_t h2;
    asm("cvt.rn.f16x2.e4m3x2 %0, %1;" : "=r"(h2) : "h"(v));
    __half2 h = *reinterpret_cast<__half2*>(&h2);
    return __half22float2(h);
}

// ---------------------------------------------------------------------------
// Prep kernels
// ---------------------------------------------------------------------------
__global__ void k_embed8(const int* __restrict__ ids, const float* __restrict__ emb) {
    int bl = blockIdx.x;
    int t  = threadIdx.x;                 // 0..127, 4 elems each
    int id = ids[bl];
    float4 v = reinterpret_cast<const float4*>(emb + (size_t)id * D_)[t];
    uint16_t lo = pack_e4m3x2(v.y * 64.0f, v.x * 64.0f);
    uint16_t hi = pack_e4m3x2(v.w * 64.0f, v.z * 64.0f);
    reinterpret_cast<uint32_t*>(g_lbf8 + (size_t)bl * D_)[t] =
        ((uint32_t)hi << 16) | lo;
}

__global__ void k_cvt_w(const float* __restrict__ w) {
    int i = blockIdx.x * blockDim.x + threadIdx.x;   // 65536 float4s
    float4 v = reinterpret_cast<const float4*>(w)[i];
    __nv_bfloat162 p0 = __floats2bfloat162_rn(v.x, v.y);
    __nv_bfloat162 p1 = __floats2bfloat162_rn(v.z, v.w);
    uint2 pk;
    pk.x = *reinterpret_cast<unsigned*>(&p0);
    pk.y = *reinterpret_cast<unsigned*>(&p1);
    reinterpret_cast<uint2*>(g_wbf)[i] = pk;
}

// Wf[col][d] fp8: col<=256 -> cos; col>=257 -> -sin((col-256)d)
__global__ void k_gen_wf8() {
    int i = blockIdx.x * 256 + threadIdx.x;     // 0..131071, 2 d's each
    int col = i >> 8;
    int d0  = (i & 255) * 2;
    float v0, v1;
    if (col < 257) {
        v0 = cosf(((col * d0) & 511) * W0_);
        v1 = cosf(((col * (d0 + 1)) & 511) * W0_);
    } else {
        int k = col - 256;
        v0 = -sinf(((k * d0) & 511) * W0_);
        v1 = -sinf(((k * (d0 + 1)) & 511) * W0_);
    }
    reinterpret_cast<uint16_t*>(g_Wf8)[i] = pack_e4m3x2(v1, v0);
}

// WiT bf16 (feeds the bf16 Wc GEMM)
__global__ void k_gen_wit() {
    int i = blockIdx.x * 256 + threadIdx.x;
    int kf = i >> 9, n = i & 511;
    float v;
    if (kf < 257) {
        float sc = (kf == 0 || kf == 256) ? (1.0f / 512.0f) : (2.0f / 512.0f);
        v = sc * cosf(((kf * n) & 511) * W0_);
    } else {
        v = -(2.0f / 512.0f) * sinf((((kf - 256) * n) & 511) * W0_);
    }
    g_WiT[i] = __float2bfloat16(v);
}

// g_Wc (bf16) -> g_Wc8 (fp8, x256)
__global__ void k_wc_cvt() {
    int i = blockIdx.x * 256 + threadIdx.x;     // 32768 threads, 8 elems each
    uint4 u = reinterpret_cast<const uint4*>(g_Wc)[i];
    __nv_bfloat162* h = reinterpret_cast<__nv_bfloat162*>(&u);
    uint16_t o[4];
#pragma unroll
    for (int q = 0; q < 4; q++) {
        float2 f = __bfloat1622float2(h[q]);
        o[q] = pack_e4m3x2(f.y * 256.0f, f.x * 256.0f);
    }
    uint2 pk;
    pk.x = ((uint32_t)o[1] << 16) | o[0];
    pk.y = ((uint32_t)o[3] << 16) | o[2];
    reinterpret_cast<uint2*>(g_Wc8)[i] = pk;
}

// ---------------------------------------------------------------------------
// Pointwise P = conj(Fa)*Fb on fp8 spectra in g_S8.
// ---------------------------------------------------------------------------
__device__ __forceinline__ void unpack8f(uint2 u, float* f) {
    uint16_t* h = reinterpret_cast<uint16_t*>(&u);
#pragma unroll
    for (int q = 0; q < 4; q++) {
        float2 t = unpack_e4m3x2(h[q]);
        f[2 * q] = t.x; f[2 * q + 1] = t.y;
    }
}
__device__ __forceinline__ uint2 pack8f(const float* f) {
    uint16_t o[4];
#pragma unroll
    for (int q = 0; q < 4; q++) o[q] = pack_e4m3x2(f[2 * q + 1], f[2 * q]);
    uint2 u;
    u.x = ((uint32_t)o[1] << 16) | o[0];
    u.y = ((uint32_t)o[3] << 16) | o[2];
    return u;
}

__global__ __launch_bounds__(128) void k_pw8(const int* __restrict__ comp) {
    int node = blockIdx.x * 4 + (threadIdx.x >> 5);
    int lane = threadIdx.x & 31;
    int b    = node / 127;
    int li   = comp[2 * node];
    int ri   = comp[2 * node + 1];

    const uint8_t* Fa = g_S8 + (size_t)(b * 128 + li) * D_;
    const uint8_t* Fb = g_S8 + (size_t)(b * 128 + ri) * D_;
    uint8_t*       P  = g_S8 + (size_t)(NLEAF + node) * D_;

    int c = 8 * lane;
    float ar[8], ai[8], br[8], bi[8];
    unpack8f(*reinterpret_cast<const uint2*>(Fa + c),       ar);
    unpack8f(*reinterpret_cast<const uint2*>(Fa + 256 + c), ai);
    unpack8f(*reinterpret_cast<const uint2*>(Fb + c),       br);
    unpack8f(*reinterpret_cast<const uint2*>(Fb + 256 + c), bi);

    float re256a = ai[0], re256b = bi[0];
    if (lane == 0) { ai[0] = 0.0f; bi[0] = 0.0f; }

    float pr[8], pi[8];
#pragma unroll
    for (int q = 0; q < 8; q++) {
        pr[q] = fmaf(ar[q], br[q],  ai[q] * bi[q]);
        pi[q] = fmaf(ar[q], bi[q], -ai[q] * br[q]);
    }
    if (lane == 0) pi[0] = re256a * re256b;

    *reinterpret_cast<uint2*>(P + c)       = pack8f(pr);
    *reinterpret_cast<uint2*>(P + 256 + c) = pack8f(pi);
}

// ===========================================================================
// bf16 WMMA GEMM (R12 engine) — ONLY for the tiny Wc GEMM (16 tiles).
// ===========================================================================
#define SK        40
#define STG       4
#define STAGE_EL  (128 * SK)
#define STAGE_BY  (STAGE_EL * 2)
#define SMEMB     (STG * STAGE_BY * 2)   // 81920 bytes

__device__ __forceinline__ uint32_t smem_u32(const void* p) {
    return (uint32_t)__cvta_generic_to_shared(p);
}
__device__ __forceinline__ void cp16(uint32_t dst, const void* src) {
    asm volatile("cp.async.cg.shared.global [%0], [%1], 16;" :: "r"(dst), "l"(src));
}

__global__ __launch_bounds__(256) void k_gemm_bf(const __nv_bfloat16* __restrict__ A,
                                                 const __nv_bfloat16* __restrict__ Bm,
                                                 __nv_bfloat16* __restrict__ outp) {
    extern __shared__ __nv_bfloat16 dsm[];
    __nv_bfloat16* sA = dsm;
    __nv_bfloat16* sB = dsm + STG * STAGE_EL;

    int tid  = threadIdx.x;
    int warp = tid >> 5;
    int lane = tid & 31;
    int wm   = warp & 3;
    int wn   = warp >> 2;
    int m0   = blockIdx.y * 128;
    int n0   = blockIdx.x * 128;

    int row     = tid >> 1;
    int c16base = (tid & 1) * 2;
    const __nv_bfloat16* gA = A  + (size_t)(m0 + row) * D_ + c16base * 8;
    const __nv_bfloat16* gB = Bm + (size_t)(n0 + row) * D_ + c16base * 8;
    uint32_t dA = smem_u32(sA + row * SK + c16base * 8);
    uint32_t dB = smem_u32(sB + row * SK + c16base * 8);

#define PFB(s, kt)                                                            \
    do {                                                                      \
        cp16(dA + (s) * STAGE_BY, gA + (kt) * 32);                            \
        cp16(dA + (s) * STAGE_BY + 16, gA + (kt) * 32 + 8);                   \
        cp16(dB + (s) * STAGE_BY, gB + (kt) * 32);                            \
        cp16(dB + (s) * STAGE_BY + 16, gB + (kt) * 32 + 8);                   \
    } while (0)

    wmma::fragment<wmma::accumulator, 16, 16, 16, float> acc[2][4];
#pragma unroll
    for (int mi = 0; mi < 2; mi++)
#pragma unroll
        for (int ni = 0; ni < 4; ni++)
            wmma::fill_fragment(acc[mi][ni], 0.0f);

    PFB(0, 0); asm volatile("cp.async.commit_group;");
    PFB(1, 1); asm volatile("cp.async.commit_group;");
    PFB(2, 2); asm volatile("cp.async.commit_group;");

    for (int kt = 0; kt < 16; kt++) {
        asm volatile("cp.async.wait_group 2;");
        __syncthreads();
        if (kt + 3 < 16) PFB((kt + 3) & 3, kt + 3);
        asm volatile("cp.async.commit_group;");

        int cur = kt & 3;
        const __nv_bfloat16* cA = sA + cur * STAGE_EL;
        const __nv_bfloat16* cB = sB + cur * STAGE_EL;
#pragma unroll
        for (int ks = 0; ks < 2; ks++) {
            wmma::fragment<wmma::matrix_a, 16, 16, 16, __nv_bfloat16, wmma::row_major> af[2];
            wmma::fragment<wmma::matrix_b, 16, 16, 16, __nv_bfloat16, wmma::col_major> bf[4];
#pragma unroll
            for (int mi = 0; mi < 2; mi++)
                wmma::load_matrix_sync(af[mi], &cA[(wm * 32 + mi * 16) * SK + ks * 16], SK);
#pragma unroll
            for (int ni = 0; ni < 4; ni++)
                wmma::load_matrix_sync(bf[ni], &cB[(wn * 64 + ni * 16) * SK + ks * 16], SK);
#pragma unroll
            for (int mi = 0; mi < 2; mi++)
#pragma unroll
                for (int ni = 0; ni < 4; ni++)
                    wmma::mma_sync(acc[mi][ni], af[mi], bf[ni], acc[mi][ni]);
        }
        __syncthreads();
    }
#undef PFB

    float* Csw = reinterpret_cast<float*>(dsm) + warp * 320;
    int er = lane >> 1;
    int ec = (lane & 1) * 8;
#pragma unroll
    for (int mi = 0; mi < 2; mi++)
#pragma unroll
        for (int ni = 0; ni < 4; ni++) {
            __syncwarp();
            wmma::store_matrix_sync(Csw, acc[mi][ni], 20, wmma::mem_row_major);
            __syncwarp();
            int gn = n0 + wn * 64 + ni * 16 + ec;
            int gm = m0 + wm * 32 + mi * 16 + er;
            __nv_bfloat162 p0 = __floats2bfloat162_rn(Csw[er * 20 + ec + 0], Csw[er * 20 + ec + 1]);
            __nv_bfloat162 p1 = __floats2bfloat162_rn(Csw[er * 20 + ec + 2], Csw[er * 20 + ec + 3]);
            __nv_bfloat162 p2 = __floats2bfloat162_rn(Csw[er * 20 + ec + 4], Csw[er * 20 + ec + 5]);
            __nv_bfloat162 p3 = __floats2bfloat162_rn(Csw[er * 20 + ec + 6], Csw[er * 20 + ec + 7]);
            uint4 pk;
            pk.x = *reinterpret_cast<unsigned*>(&p0);
            pk.y = *reinterpret_cast<unsigned*>(&p1);
            pk.z = *reinterpret_cast<unsigned*>(&p2);
            pk.w = *reinterpret_cast<unsigned*>(&p3);
            *reinterpret_cast<uint4*>(outp + (size_t)gm * D_ + gn) = pk;
        }
}

// ===========================================================================
// FP8 e4m3 GEMM v2: BK=128 bytes, 3-stage ring, 4 K-iterations.
// C[128x128] = A[128x512] * B[128x512]^T, fp32 accum.
// 8 warps (4M x 2N); warp tile 32x64 = 2 m-frags x 8 n-frags; 64 mma/barrier.
// Row stride 144B: STS and fragment LDS both provably conflict-free.
// MODE 0: store fp8 spectra (scale 1/64) to outp rows (ld 512)
// MODE 1: logits sigmoid(acc/256 + b); rows <NLEAF leaf-map, else internal-map
// ===========================================================================
#define SK8       144                 // bytes per row in smem
#define STG8      3
#define STAGE8    (128 * SK8)         // 18432 bytes per stage per matrix
#define SMEMB8    (STG8 * STAGE8 * 2) // 110592 bytes

__device__ __forceinline__ void mma8(float* c, uint32_t a0, uint32_t a1,
                                     uint32_t a2, uint32_t a3,
                                     uint32_t b0, uint32_t b1) {
    asm volatile(
        "mma.sync.aligned.m16n8k32.row.col.f32.e4m3.e4m3.f32 "
        "{%0,%1,%2,%3}, {%4,%5,%6,%7}, {%8,%9}, {%0,%1,%2,%3};"
        : "+f"(c[0]), "+f"(c[1]), "+f"(c[2]), "+f"(c[3])
        : "r"(a0), "r"(a1), "r"(a2), "r"(a3), "r"(b0), "r"(b1));
}

template <int MODE>
__global__ __launch_bounds__(256) void k_gemm8(const uint8_t* __restrict__ A,
                                               const uint8_t* __restrict__ Bm,
                                               const float* __restrict__ lb,
                                               void* __restrict__ outp) {
    extern __shared__ char dsm8[];
    char* sA = dsm8;                      // [STG8][128*SK8]
    char* sB = dsm8 + STG8 * STAGE8;

    int tid  = threadIdx.x;
    int warp = tid >> 5;
    int lane = tid & 31;
    int g    = lane >> 2;                 // 0..7
    int tig  = lane & 3;                  // 0..3
    int wm   = warp & 3;                  // M: 32 rows each
    int wn   = warp >> 2;                 // N: 64 cols each
    int m0   = blockIdx.y * 128;
    int n0   = blockIdx.x * 128;

    // staging: thread -> row tid>>1, 4 x 16B chunks at base (tid&1)*4
    int srow = tid >> 1;
    int sc16 = (tid & 1) * 4;
    const uint8_t* gA = A  + (size_t)(m0 + srow) * D_ + sc16 * 16;
    const uint8_t* gB = Bm + (size_t)(n0 + srow) * D_ + sc16 * 16;
    uint32_t dA = smem_u32(sA + srow * SK8 + sc16 * 16);
    uint32_t dB = smem_u32(sB + srow * SK8 + sc16 * 16);

#define PF8(s, kt)                                                            \
    do {                                                                      \
        _Pragma("unroll")                                                     \
        for (int c = 0; c < 4; c++) {                                         \
            cp16(dA + (s) * STAGE8 + c * 16, gA + (kt) * 128 + c * 16);       \
            cp16(dB + (s) * STAGE8 + c * 16, gB + (kt) * 128 + c * 16);       \
        }                                                                     \
    } while (0)

    float acc[2][8][4];
#pragma unroll
    for (int mi = 0; mi < 2; mi++)
#pragma unroll
        for (int nj = 0; nj < 8; nj++)
#pragma unroll
            for (int q = 0; q < 4; q++) acc[mi][nj][q] = 0.0f;

    PF8(0, 0); asm volatile("cp.async.commit_group;");
    PF8(1, 1); asm volatile("cp.async.commit_group;");

    for (int kt = 0; kt < 4; kt++) {
        asm volatile("cp.async.wait_group 1;");
        __syncthreads();
        if (kt + 2 < 4) PF8((kt + 2) % 3, kt + 2);
        asm volatile("cp.async.commit_group;");

        const char* cA = sA + (kt % 3) * STAGE8;
        const char* cB = sB + (kt % 3) * STAGE8;
#pragma unroll
        for (int kc = 0; kc < 4; kc++) {
            uint32_t bfr[8][2];
#pragma unroll
            for (int nj = 0; nj < 8; nj++) {
                const char* pb = cB + (wn * 64 + 8 * nj + g) * SK8 + kc * 32 + 4 * tig;
                bfr[nj][0] = *reinterpret_cast<const uint32_t*>(pb);
                bfr[nj][1] = *reinterpret_cast<const uint32_t*>(pb + 16);
            }
#pragma unroll
            for (int mi = 0; mi < 2; mi++) {
                const char* pa = cA + (wm * 32 + mi * 16 + g) * SK8 + kc * 32 + 4 * tig;
                uint32_t a0 = *reinterpret_cast<const uint32_t*>(pa);
                uint32_t a1 = *reinterpret_cast<const uint32_t*>(pa + 8 * SK8);
                uint32_t a2 = *reinterpret_cast<const uint32_t*>(pa + 16);
                uint32_t a3 = *reinterpret_cast<const uint32_t*>(pa + 8 * SK8 + 16);
#pragma unroll
                for (int nj = 0; nj < 8; nj++)
                    mma8(acc[mi][nj], a0, a1, a2, a3, bfr[nj][0], bfr[nj][1]);
            }
        }
        __syncthreads();
    }
#undef PF8

    // Epilogue (fragment-direct: rows g, g+8; cols 2*tig, 2*tig+1)
    const float s = (MODE == 0) ? (1.0f / 64.0f) : (1.0f / 256.0f);
#pragma unroll
    for (int mi = 0; mi < 2; mi++) {
#pragma unroll
        for (int nj = 0; nj < 8; nj++) {
            int col = n0 + wn * 64 + 8 * nj + 2 * tig;
            int r0  = m0 + wm * 32 + mi * 16 + g;
            float c0 = acc[mi][nj][0] * s, c1 = acc[mi][nj][1] * s;
            float c2 = acc[mi][nj][2] * s, c3 = acc[mi][nj][3] * s;
            if (MODE == 0) {
                uint8_t* ob = reinterpret_cast<uint8_t*>(outp);
                *reinterpret_cast<uint16_t*>(ob + (size_t)r0 * D_ + col) =
                    pack_e4m3x2(c1, c0);
                *reinterpret_cast<uint16_t*>(ob + (size_t)(r0 + 8) * D_ + col) =
                    pack_e4m3x2(c3, c2);
            } else {
                float2 bb = *reinterpret_cast<const float2*>(&lb[col]);
#pragma unroll
                for (int h = 0; h < 2; h++) {
                    int gm = r0 + 8 * h;
                    int orow;
                    if (gm < NLEAF) {
                        orow = (gm >> 7) * NODES_ + (gm & 127);
                    } else {
                        int q  = gm - NLEAF;
                        int bx = q / 127;
                        orow = bx * NODES_ + L_ + (q - bx * 127);
                    }
                    float x0 = (h ? c2 : c0) + bb.x;
                    float x1 = (h ? c3 : c1) + bb.y;
                    float2 o;
                    o.x = 1.0f / (1.0f + __expf(-x0));
                    o.y = 1.0f / (1.0f + __expf(-x1));
                    *reinterpret_cast<float2*>(
                        reinterpret_cast<float*>(outp) + (size_t)orow * C_ + col) = o;
                }
            }
        }
    }
}

// ---------------------------------------------------------------------------
// Launch
// ---------------------------------------------------------------------------
extern "C" void kernel_launch(void* const* d_in, const int* in_sizes, int n_in,
                              void* d_out, int out_size) {
    const int*   ids  = nullptr;
    const int*   comp = nullptr;
    const float* emb  = nullptr;
    const float* lw   = nullptr;
    const float* lb   = nullptr;

    for (int i = 0; i < n_in; i++) {
        switch (in_sizes[i]) {
            case 16384:    ids  = (const int*)d_in[i];   break;  // leaf_content_id
            case 32512:    comp = (const int*)d_in[i];   break;  // composition_info
            case 25600000: emb  = (const float*)d_in[i]; break;  // emb_weight
            case 262144:   lw   = (const float*)d_in[i]; break;  // lin_w
            case 512:      lb   = (const float*)d_in[i]; break;  // lin_b
            default: break;                                       // content_mask
        }
    }

    float* out = (float*)d_out;

    __nv_bfloat16 *p_wbf, *p_WiT, *p_Wc;
    uint8_t *p_lbf8, *p_Wf8, *p_Wc8, *p_S8;
    cudaGetSymbolAddress((void**)&p_wbf,  g_wbf);
    cudaGetSymbolAddress((void**)&p_WiT,  g_WiT);
    cudaGetSymbolAddress((void**)&p_Wc,   g_Wc);
    cudaGetSymbolAddress((void**)&p_lbf8, g_lbf8);
    cudaGetSymbolAddress((void**)&p_Wf8,  g_Wf8);
    cudaGetSymbolAddress((void**)&p_Wc8,  g_Wc8);
    cudaGetSymbolAddress((void**)&p_S8,   g_S8);

    static bool attr_done = false;
    if (!attr_done) {
        cudaFuncSetAttribute(k_gemm_bf,  cudaFuncAttributeMaxDynamicSharedMemorySize, SMEMB);
        cudaFuncSetAttribute(k_gemm8<0>, cudaFuncAttributeMaxDynamicSharedMemorySize, SMEMB8);
        cudaFuncSetAttribute(k_gemm8<1>, cudaFuncAttributeMaxDynamicSharedMemorySize, SMEMB8);
        attr_done = true;
    }

    k_embed8 <<<NLEAF, 128>>>(ids, emb);
    k_cvt_w  <<<256, 256>>>(lw);
    k_gen_wf8<<<512, 256>>>();
    k_gen_wit<<<1024, 256>>>();

    k_gemm_bf<<<dim3(4, 4), 256, SMEMB>>>(p_wbf, p_WiT, p_Wc);                // Wc bf16
    k_wc_cvt <<<128, 256>>>();                                                 // Wc -> fp8
    // forward FFT: leaf spectra into g_S8 rows [0, NLEAF)
    k_gemm8<0><<<dim3(4, NLEAF / 128), 256, SMEMB8>>>(p_lbf8, p_Wf8, lb, (void*)p_S8);
    // pointwise products into g_S8 rows [NLEAF, NALL)
    k_pw8    <<<NINT / 4, 128>>>(comp);
    // one combined logits GEMM over all 32640 spectra rows
    k_gemm8<1><<<dim3(4, NALL / 128), 256, SMEMB8>>>(p_S8, p_Wc8, lb, (void*)out);
}

// round 17
// speedup vs baseline: 1.5335x; 1.0320x over previous
#include <cuda_runtime.h>
#include <cuda_bf16.h>
#include <cuda_fp16.h>
#include <cuda_fp8.h>
#include <mma.h>
#include <cstdint>

using namespace nvcuda;

#define B_     128
#define L_     128
#define D_     512
#define C_     512
#define NODES_ 255
#define NLEAF  (B_ * L_)        // 16384
#define NINT   (B_ * (L_ - 1)) // 16256
#define NALL   (NLEAF + NINT)   // 32640
#define W0_    0.01227184630308513f   // 2*pi/512

// Scratch.
__device__ __align__(16) uint8_t g_lbf8[(size_t)NLEAF * D_]; // leaf fp8 (x64)
__device__ __align__(16) uint8_t g_Wf8 [(size_t)D_ * D_];    // fwd DFT fp8 (x1)
__device__ __align__(16) uint8_t g_Wc8 [(size_t)C_ * D_];    // Wc fp8 (x256)
__device__ __align__(16) uint8_t g_S8  [(size_t)NALL * D_];  // [leaf spectra; P spectra]
__device__ __nv_bfloat16 g_wbf[(size_t)C_ * D_];             // lin_w bf16 (Wc GEMM)
__device__ __nv_bfloat16 g_WiT[(size_t)D_ * D_];             // inv DFT^T bf16
__device__ __nv_bfloat16 g_Wc [(size_t)C_ * D_];             // Wc bf16

// ---------------------------------------------------------------------------
// fp8 helpers (e4m3)
// ---------------------------------------------------------------------------
__device__ __forceinline__ uint16_t pack_e4m3x2(float hi, float lo) {
    uint16_t r;
    asm("cvt.rn.satfinite.e4m3x2.f32 %0, %1, %2;" : "=h"(r) : "f"(hi), "f"(lo));
    return r;
}
__device__ __forceinline__ float2 unpack_e4m3x2(uint16_t v) {
    uint32_t h2;
    asm("cvt.rn.f16x2.e4m3x2 %0, %1;" : "=r"(h2) : "h"(v));
    __half2 h = *reinterpret_cast<__half2*>(&h2);
    return __half22float2(h);
}

// ---------------------------------------------------------------------------
// Prep kernels
// ---------------------------------------------------------------------------
__global__ void k_embed8(const int* __restrict__ ids, const float* __restrict__ emb) {
    int bl = blockIdx.x;
    int t  = threadIdx.x;                 // 0..127, 4 elems each
    int id = ids[bl];
    float4 v = reinterpret_cast<const float4*>(emb + (size_t)id * D_)[t];
    uint16_t lo = pack_e4m3x2(v.y * 64.0f, v.x * 64.0f);
    uint16_t hi = pack_e4m3x2(v.w * 64.0f, v.z * 64.0f);
    reinterpret_cast<uint32_t*>(g_lbf8 + (size_t)bl * D_)[t] =
        ((uint32_t)hi << 16) | lo;
}

__global__ void k_cvt_w(const float* __restrict__ w) {
    int i = blockIdx.x * blockDim.x + threadIdx.x;   // 65536 float4s
    float4 v = reinterpret_cast<const float4*>(w)[i];
    __nv_bfloat162 p0 = __floats2bfloat162_rn(v.x, v.y);
    __nv_bfloat162 p1 = __floats2bfloat162_rn(v.z, v.w);
    uint2 pk;
    pk.x = *reinterpret_cast<unsigned*>(&p0);
    pk.y = *reinterpret_cast<unsigned*>(&p1);
    reinterpret_cast<uint2*>(g_wbf)[i] = pk;
}

// Wf[col][d] fp8: col<=256 -> cos; col>=257 -> -sin((col-256)d)
__global__ void k_gen_wf8() {
    int i = blockIdx.x * 256 + threadIdx.x;     // 0..131071, 2 d's each
    int col = i >> 8;
    int d0  = (i & 255) * 2;
    float v0, v1;
    if (col < 257) {
        v0 = cosf(((col * d0) & 511) * W0_);
        v1 = cosf(((col * (d0 + 1)) & 511) * W0_);
    } else {
        int k = col - 256;
        v0 = -sinf(((k * d0) & 511) * W0_);
        v1 = -sinf(((k * (d0 + 1)) & 511) * W0_);
    }
    reinterpret_cast<uint16_t*>(g_Wf8)[i] = pack_e4m3x2(v1, v0);
}

// WiT bf16 (feeds the bf16 Wc GEMM)
__global__ void k_gen_wit() {
    int i = blockIdx.x * 256 + threadIdx.x;
    int kf = i >> 9, n = i & 511;
    float v;
    if (kf < 257) {
        float sc = (kf == 0 || kf == 256) ? (1.0f / 512.0f) : (2.0f / 512.0f);
        v = sc * cosf(((kf * n) & 511) * W0_);
    } else {
        v = -(2.0f / 512.0f) * sinf((((kf - 256) * n) & 511) * W0_);
    }
    g_WiT[i] = __float2bfloat16(v);
}

// g_Wc (bf16) -> g_Wc8 (fp8, x256)
__global__ void k_wc_cvt() {
    int i = blockIdx.x * 256 + threadIdx.x;     // 32768 threads, 8 elems each
    uint4 u = reinterpret_cast<const uint4*>(g_Wc)[i];
    __nv_bfloat162* h = reinterpret_cast<__nv_bfloat162*>(&u);
    uint16_t o[4];
#pragma unroll
    for (int q = 0; q < 4; q++) {
        float2 f = __bfloat1622float2(h[q]);
        o[q] = pack_e4m3x2(f.y * 256.0f, f.x * 256.0f);
    }
    uint2 pk;
    pk.x = ((uint32_t)o[1] << 16) | o[0];
    pk.y = ((uint32_t)o[3] << 16) | o[2];
    reinterpret_cast<uint2*>(g_Wc8)[i] = pk;
}

// ---------------------------------------------------------------------------
// Pointwise P = conj(Fa)*Fb on fp8 spectra in g_S8.
// ---------------------------------------------------------------------------
__device__ __forceinline__ void unpack8f(uint2 u, float* f) {
    uint16_t* h = reinterpret_cast<uint16_t*>(&u);
#pragma unroll
    for (int q = 0; q < 4; q++) {
        float2 t = unpack_e4m3x2(h[q]);
        f[2 * q] = t.x; f[2 * q + 1] = t.y;
    }
}
__device__ __forceinline__ uint2 pack8f(const float* f) {
    uint16_t o[4];
#pragma unroll
    for (int q = 0; q < 4; q++) o[q] = pack_e4m3x2(f[2 * q + 1], f[2 * q]);
    uint2 u;
    u.x = ((uint32_t)o[1] << 16) | o[0];
    u.y = ((uint32_t)o[3] << 16) | o[2];
    return u;
}

__global__ __launch_bounds__(128) void k_pw8(const int* __restrict__ comp) {
    int node = blockIdx.x * 4 + (threadIdx.x >> 5);
    int lane = threadIdx.x & 31;
    int b    = node / 127;
    int li   = comp[2 * node];
    int ri   = comp[2 * node + 1];

    const uint8_t* Fa = g_S8 + (size_t)(b * 128 + li) * D_;
    const uint8_t* Fb = g_S8 + (size_t)(b * 128 + ri) * D_;
    uint8_t*       P  = g_S8 + (size_t)(NLEAF + node) * D_;

    int c = 8 * lane;
    float ar[8], ai[8], br[8], bi[8];
    unpack8f(*reinterpret_cast<const uint2*>(Fa + c),       ar);
    unpack8f(*reinterpret_cast<const uint2*>(Fa + 256 + c), ai);
    unpack8f(*reinterpret_cast<const uint2*>(Fb + c),       br);
    unpack8f(*reinterpret_cast<const uint2*>(Fb + 256 + c), bi);

    float re256a = ai[0], re256b = bi[0];
    if (lane == 0) { ai[0] = 0.0f; bi[0] = 0.0f; }

    float pr[8], pi[8];
#pragma unroll
    for (int q = 0; q < 8; q++) {
        pr[q] = fmaf(ar[q], br[q],  ai[q] * bi[q]);
        pi[q] = fmaf(ar[q], bi[q], -ai[q] * br[q]);
    }
    if (lane == 0) pi[0] = re256a * re256b;

    *reinterpret_cast<uint2*>(P + c)       = pack8f(pr);
    *reinterpret_cast<uint2*>(P + 256 + c) = pack8f(pi);
}

// ===========================================================================
// bf16 WMMA GEMM (R12 engine) — ONLY for the tiny Wc GEMM (16 tiles).
// ===========================================================================
#define SK        40
#define STG       4
#define STAGE_EL  (128 * SK)
#define STAGE_BY  (STAGE_EL * 2)
#define SMEMB     (STG * STAGE_BY * 2)   // 81920 bytes

__device__ __forceinline__ uint32_t smem_u32(const void* p) {
    return (uint32_t)__cvta_generic_to_shared(p);
}
__device__ __forceinline__ void cp16(uint32_t dst, const void* src) {
    asm volatile("cp.async.cg.shared.global [%0], [%1], 16;" :: "r"(dst), "l"(src));
}

__global__ __launch_bounds__(256) void k_gemm_bf(const __nv_bfloat16* __restrict__ A,
                                                 const __nv_bfloat16* __restrict__ Bm,
                                                 __nv_bfloat16* __restrict__ outp) {
    extern __shared__ __nv_bfloat16 dsm[];
    __nv_bfloat16* sA = dsm;
    __nv_bfloat16* sB = dsm + STG * STAGE_EL;

    int tid  = threadIdx.x;
    int warp = tid >> 5;
    int lane = tid & 31;
    int wm   = warp & 3;
    int wn   = warp >> 2;
    int m0   = blockIdx.y * 128;
    int n0   = blockIdx.x * 128;

    int row     = tid >> 1;
    int c16base = (tid & 1) * 2;
    const __nv_bfloat16* gA = A  + (size_t)(m0 + row) * D_ + c16base * 8;
    const __nv_bfloat16* gB = Bm + (size_t)(n0 + row) * D_ + c16base * 8;
    uint32_t dA = smem_u32(sA + row * SK + c16base * 8);
    uint32_t dB = smem_u32(sB + row * SK + c16base * 8);

#define PFB(s, kt)                                                            \
    do {                                                                      \
        cp16(dA + (s) * STAGE_BY, gA + (kt) * 32);                            \
        cp16(dA + (s) * STAGE_BY + 16, gA + (kt) * 32 + 8);                   \
        cp16(dB + (s) * STAGE_BY, gB + (kt) * 32);                            \
        cp16(dB + (s) * STAGE_BY + 16, gB + (kt) * 32 + 8);                   \
    } while (0)

    wmma::fragment<wmma::accumulator, 16, 16, 16, float> acc[2][4];
#pragma unroll
    for (int mi = 0; mi < 2; mi++)
#pragma unroll
        for (int ni = 0; ni < 4; ni++)
            wmma::fill_fragment(acc[mi][ni], 0.0f);

    PFB(0, 0); asm volatile("cp.async.commit_group;");
    PFB(1, 1); asm volatile("cp.async.commit_group;");
    PFB(2, 2); asm volatile("cp.async.commit_group;");

    for (int kt = 0; kt < 16; kt++) {
        asm volatile("cp.async.wait_group 2;");
        __syncthreads();
        if (kt + 3 < 16) PFB((kt + 3) & 3, kt + 3);
        asm volatile("cp.async.commit_group;");

        int cur = kt & 3;
        const __nv_bfloat16* cA = sA + cur * STAGE_EL;
        const __nv_bfloat16* cB = sB + cur * STAGE_EL;
#pragma unroll
        for (int ks = 0; ks < 2; ks++) {
            wmma::fragment<wmma::matrix_a, 16, 16, 16, __nv_bfloat16, wmma::row_major> af[2];
            wmma::fragment<wmma::matrix_b, 16, 16, 16, __nv_bfloat16, wmma::col_major> bf[4];
#pragma unroll
            for (int mi = 0; mi < 2; mi++)
                wmma::load_matrix_sync(af[mi], &cA[(wm * 32 + mi * 16) * SK + ks * 16], SK);
#pragma unroll
            for (int ni = 0; ni < 4; ni++)
                wmma::load_matrix_sync(bf[ni], &cB[(wn * 64 + ni * 16) * SK + ks * 16], SK);
#pragma unroll
            for (int mi = 0; mi < 2; mi++)
#pragma unroll
                for (int ni = 0; ni < 4; ni++)
                    wmma::mma_sync(acc[mi][ni], af[mi], bf[ni], acc[mi][ni]);
        }
        __syncthreads();
    }
#undef PFB

    float* Csw = reinterpret_cast<float*>(dsm) + warp * 320;
    int er = lane >> 1;
    int ec = (lane & 1) * 8;
#pragma unroll
    for (int mi = 0; mi < 2; mi++)
#pragma unroll
        for (int ni = 0; ni < 4; ni++) {
            __syncwarp();
            wmma::store_matrix_sync(Csw, acc[mi][ni], 20, wmma::mem_row_major);
            __syncwarp();
            int gn = n0 + wn * 64 + ni * 16 + ec;
            int gm = m0 + wm * 32 + mi * 16 + er;
            __nv_bfloat162 p0 = __floats2bfloat162_rn(Csw[er * 20 + ec + 0], Csw[er * 20 + ec + 1]);
            __nv_bfloat162 p1 = __floats2bfloat162_rn(Csw[er * 20 + ec + 2], Csw[er * 20 + ec + 3]);
            __nv_bfloat162 p2 = __floats2bfloat162_rn(Csw[er * 20 + ec + 4], Csw[er * 20 + ec + 5]);
            __nv_bfloat162 p3 = __floats2bfloat162_rn(Csw[er * 20 + ec + 6], Csw[er * 20 + ec + 7]);
            uint4 pk;
            pk.x = *reinterpret_cast<unsigned*>(&p0);
            pk.y = *reinterpret_cast<unsigned*>(&p1);
            pk.z = *reinterpret_cast<unsigned*>(&p2);
            pk.w = *reinterpret_cast<unsigned*>(&p3);
            *reinterpret_cast<uint4*>(outp + (size_t)gm * D_ + gn) = pk;
        }
}

// ===========================================================================
// FP8 e4m3 GEMM v3: BK=128B, 3-stage ring, ldmatrix fragment loads.
// C[128x128] = A[128x512] * B[128x512]^T, fp32 accum.
// 8 warps (4M x 2N); warp tile 32x64; per kc: 2 LDSM.x4 (A) + 8 LDSM.x2 (B)
// feed 16 QMMA. Row stride 144B -> each matrix's 8 rows hit distinct 16B
// bank-groups (9r mod 8 = r): conflict-free.
// MODE 0: store fp8 spectra (scale 1/64) to outp rows (ld 512)
// MODE 1: logits sigmoid(acc/256 + b); rows <NLEAF leaf-map, else internal-map
// ===========================================================================
#define SK8       144                 // bytes per row in smem
#define STG8      3
#define STAGE8    (128 * SK8)         // 18432 bytes per stage per matrix
#define SMEMB8    (STG8 * STAGE8 * 2) // 110592 bytes

__device__ __forceinline__ void mma8(float* c, uint32_t a0, uint32_t a1,
                                     uint32_t a2, uint32_t a3,
                                     uint32_t b0, uint32_t b1) {
    asm volatile(
        "mma.sync.aligned.m16n8k32.row.col.f32.e4m3.e4m3.f32 "
        "{%0,%1,%2,%3}, {%4,%5,%6,%7}, {%8,%9}, {%0,%1,%2,%3};"
        : "+f"(c[0]), "+f"(c[1]), "+f"(c[2]), "+f"(c[3])
        : "r"(a0), "r"(a1), "r"(a2), "r"(a3), "r"(b0), "r"(b1));
}
__device__ __forceinline__ void ldsm4(uint32_t& r0, uint32_t& r1,
                                      uint32_t& r2, uint32_t& r3, uint32_t addr) {
    asm volatile("ldmatrix.sync.aligned.m8n8.x4.shared.b16 {%0,%1,%2,%3}, [%4];"
                 : "=r"(r0), "=r"(r1), "=r"(r2), "=r"(r3) : "r"(addr));
}
__device__ __forceinline__ void ldsm2(uint32_t& r0, uint32_t& r1, uint32_t addr) {
    asm volatile("ldmatrix.sync.aligned.m8n8.x2.shared.b16 {%0,%1}, [%2];"
                 : "=r"(r0), "=r"(r1) : "r"(addr));
}

template <int MODE>
__global__ __launch_bounds__(256) void k_gemm8(const uint8_t* __restrict__ A,
                                               const uint8_t* __restrict__ Bm,
                                               const float* __restrict__ lb,
                                               void* __restrict__ outp) {
    extern __shared__ char dsm8[];
    char* sA = dsm8;                      // [STG8][128*SK8]
    char* sB = dsm8 + STG8 * STAGE8;

    int tid  = threadIdx.x;
    int warp = tid >> 5;
    int lane = tid & 31;
    int g    = lane >> 2;                 // 0..7
    int tig  = lane & 3;                  // 0..3
    int wm   = warp & 3;                  // M: 32 rows each
    int wn   = warp >> 2;                 // N: 64 cols each
    int m0   = blockIdx.y * 128;
    int n0   = blockIdx.x * 128;

    // staging: thread -> row tid>>1, 4 x 16B chunks at base (tid&1)*4
    int srow = tid >> 1;
    int sc16 = (tid & 1) * 4;
    const uint8_t* gA = A  + (size_t)(m0 + srow) * D_ + sc16 * 16;
    const uint8_t* gB = Bm + (size_t)(n0 + srow) * D_ + sc16 * 16;
    uint32_t dA = smem_u32(sA + srow * SK8 + sc16 * 16);
    uint32_t dB = smem_u32(sB + srow * SK8 + sc16 * 16);

#define PF8(s, kt)                                                            \
    do {                                                                      \
        _Pragma("unroll")                                                     \
        for (int c = 0; c < 4; c++) {                                         \
            cp16(dA + (s) * STAGE8 + c * 16, gA + (kt) * 128 + c * 16);       \
            cp16(dB + (s) * STAGE8 + c * 16, gB + (kt) * 128 + c * 16);       \
        }                                                                     \
    } while (0)

    // ldmatrix per-lane address bases (within a stage):
    //  A x4: row = wm*32 + mi*16 + (lane&15); byte off = ((lane>>4)&1)*16
    //  B x2: row = wn*64 + nj*8 + (lane&7);   byte off = ((lane>>3)&1)*16
    uint32_t sAu = smem_u32(sA);
    uint32_t sBu = smem_u32(sB);
    uint32_t aoff = (uint32_t)(wm * 32 + (lane & 15)) * SK8 + (((lane >> 4) & 1) << 4);
    uint32_t boff = (uint32_t)(wn * 64 + (lane & 7)) * SK8 + (((lane >> 3) & 1) << 4);

    float acc[2][8][4];
#pragma unroll
    for (int mi = 0; mi < 2; mi++)
#pragma unroll
        for (int nj = 0; nj < 8; nj++)
#pragma unroll
            for (int q = 0; q < 4; q++) acc[mi][nj][q] = 0.0f;

    PF8(0, 0); asm volatile("cp.async.commit_group;");
    PF8(1, 1); asm volatile("cp.async.commit_group;");

    for (int kt = 0; kt < 4; kt++) {
        asm volatile("cp.async.wait_group 1;");
        __syncthreads();
        if (kt + 2 < 4) PF8((kt + 2) % 3, kt + 2);
        asm volatile("cp.async.commit_group;");

        uint32_t aS = sAu + (kt % 3) * STAGE8 + aoff;
        uint32_t bS = sBu + (kt % 3) * STAGE8 + boff;
#pragma unroll
        for (int kc = 0; kc < 4; kc++) {
            uint32_t bfr[8][2];
#pragma unroll
            for (int nj = 0; nj < 8; nj++)
                ldsm2(bfr[nj][0], bfr[nj][1], bS + nj * (8 * SK8) + kc * 32);
#pragma unroll
            for (int mi = 0; mi < 2; mi++) {
                uint32_t a0, a1, a2, a3;
                ldsm4(a0, a1, a2, a3, aS + mi * (16 * SK8) + kc * 32);
#pragma unroll
                for (int nj = 0; nj < 8; nj++)
                    mma8(acc[mi][nj], a0, a1, a2, a3, bfr[nj][0], bfr[nj][1]);
            }
        }
        __syncthreads();
    }
#undef PF8

    // Epilogue (fragment-direct: rows g, g+8; cols 2*tig, 2*tig+1)
    const float s = (MODE == 0) ? (1.0f / 64.0f) : (1.0f / 256.0f);
#pragma unroll
    for (int mi = 0; mi < 2; mi++) {
#pragma unroll
        for (int nj = 0; nj < 8; nj++) {
            int col = n0 + wn * 64 + 8 * nj + 2 * tig;
            int r0  = m0 + wm * 32 + mi * 16 + g;
            float c0 = acc[mi][nj][0] * s, c1 = acc[mi][nj][1] * s;
            float c2 = acc[mi][nj][2] * s, c3 = acc[mi][nj][3] * s;
            if (MODE == 0) {
                uint8_t* ob = reinterpret_cast<uint8_t*>(outp);
                *reinterpret_cast<uint16_t*>(ob + (size_t)r0 * D_ + col) =
                    pack_e4m3x2(c1, c0);
                *reinterpret_cast<uint16_t*>(ob + (size_t)(r0 + 8) * D_ + col) =
                    pack_e4m3x2(c3, c2);
            } else {
                float2 bb = *reinterpret_cast<const float2*>(&lb[col]);
#pragma unroll
                for (int h = 0; h < 2; h++) {
                    int gm = r0 + 8 * h;
                    int orow;
                    if (gm < NLEAF) {
                        orow = (gm >> 7) * NODES_ + (gm & 127);
                    } else {
                        int q  = gm - NLEAF;
                        int bx = q / 127;
                        orow = bx * NODES_ + L_ + (q - bx * 127);
                    }
                    float x0 = (h ? c2 : c0) + bb.x;
                    float x1 = (h ? c3 : c1) + bb.y;
                    float2 o;
                    o.x = 1.0f / (1.0f + __expf(-x0));
                    o.y = 1.0f / (1.0f + __expf(-x1));
                    *reinterpret_cast<float2*>(
                        reinterpret_cast<float*>(outp) + (size_t)orow * C_ + col) = o;
                }
            }
        }
    }
}

// ---------------------------------------------------------------------------
// Launch
// ---------------------------------------------------------------------------
extern "C" void kernel_launch(void* const* d_in, const int* in_sizes, int n_in,
                              void* d_out, int out_size) {
    const int*   ids  = nullptr;
    const int*   comp = nullptr;
    const float* emb  = nullptr;
    const float* lw   = nullptr;
    const float* lb   = nullptr;

    for (int i = 0; i < n_in; i++) {
        switch (in_sizes[i]) {
            case 16384:    ids  = (const int*)d_in[i];   break;  // leaf_content_id
            case 32512:    comp = (const int*)d_in[i];   break;  // composition_info
            case 25600000: emb  = (const float*)d_in[i]; break;  // emb_weight
            case 262144:   lw   = (const float*)d_in[i]; break;  // lin_w
            case 512:      lb   = (const float*)d_in[i]; break;  // lin_b
            default: break;                                       // content_mask
        }
    }

    float* out = (float*)d_out;

    __nv_bfloat16 *p_wbf, *p_WiT, *p_Wc;
    uint8_t *p_lbf8, *p_Wf8, *p_Wc8, *p_S8;
    cudaGetSymbolAddress((void**)&p_wbf,  g_wbf);
    cudaGetSymbolAddress((void**)&p_WiT,  g_WiT);
    cudaGetSymbolAddress((void**)&p_Wc,   g_Wc);
    cudaGetSymbolAddress((void**)&p_lbf8, g_lbf8);
    cudaGetSymbolAddress((void**)&p_Wf8,  g_Wf8);
    cudaGetSymbolAddress((void**)&p_Wc8,  g_Wc8);
    cudaGetSymbolAddress((void**)&p_S8,   g_S8);

    static bool attr_done = false;
    if (!attr_done) {
        cudaFuncSetAttribute(k_gemm_bf,  cudaFuncAttributeMaxDynamicSharedMemorySize, SMEMB);
        cudaFuncSetAttribute(k_gemm8<0>, cudaFuncAttributeMaxDynamicSharedMemorySize, SMEMB8);
        cudaFuncSetAttribute(k_gemm8<1>, cudaFuncAttributeMaxDynamicSharedMemorySize, SMEMB8);
        attr_done = true;
    }

    k_embed8 <<<NLEAF, 128>>>(ids, emb);
    k_cvt_w  <<<256, 256>>>(lw);
    k_gen_wf8<<<512, 256>>>();
    k_gen_wit<<<1024, 256>>>();

    k_gemm_bf<<<dim3(4, 4), 256, SMEMB>>>(p_wbf, p_WiT, p_Wc);                // Wc bf16
    k_wc_cvt <<<128, 256>>>();                                                 // Wc -> fp8
    // forward FFT: leaf spectra into g_S8 rows [0, NLEAF)
    k_gemm8<0><<<dim3(4, NLEAF / 128), 256, SMEMB8>>>(p_lbf8, p_Wf8, lb, (void*)p_S8);
    // pointwise products into g_S8 rows [NLEAF, NALL)
    k_pw8    <<<NINT / 4, 128>>>(comp);
    // one combined logits GEMM over all 32640 spectra rows
    k_gemm8<1><<<dim3(4, NALL / 128), 256, SMEMB8>>>(p_S8, p_Wc8, lb, (void*)out);
}